// round 2
// baseline (speedup 1.0000x reference)
#include <cuda_runtime.h>
#include <math.h>

#define NN 100000
#define DD 128
#define EE 600000
#define HH 8

// ---------------- scratch (device globals; no allocation allowed) -------------
__device__ __align__(16) float g_Q[NN * DD];
__device__ __align__(16) float g_K[NN * DD];
__device__ __align__(16) float g_V[NN * DD];
__device__ __align__(16) float g_Z[NN * DD];   // starts as residual, atomics add aggr
__device__ __align__(16) float g_scores[EE * HH];
__device__ int   g_smax[NN * HH];
__device__ float g_ssum[NN * HH];
__device__ __align__(16) float g_eaq[DD];
__device__ __align__(16) float g_eak[DD];
__device__ int g_src[EE];
__device__ int g_dst[EE];
__device__ int g_is64;

// ---------------- helpers ----------------------------------------------------
__device__ __forceinline__ int f2o(float f) {
    int i = __float_as_int(f);
    return (i >= 0) ? i : (i ^ 0x7fffffff);
}
__device__ __forceinline__ float o2f(int i) {
    return (i >= 0) ? __int_as_float(i) : __int_as_float(i ^ 0x7fffffff);
}

// ---------------- dtype detect + index conversion -----------------------------
// If edge_index is int64 with values < 2^31, every odd 32-bit word (high half)
// is zero. If it is int32, odd words are random node ids -> OR != 0 w.h.p.
__global__ void k_detect(const int* __restrict__ w) {
    __shared__ int red[256];
    int acc = 0;
    for (int i = threadIdx.x; i < 4096; i += 256) acc |= w[2 * i + 1];
    red[threadIdx.x] = acc;
    __syncthreads();
    for (int s = 128; s > 0; s >>= 1) {
        if (threadIdx.x < s) red[threadIdx.x] |= red[threadIdx.x + s];
        __syncthreads();
    }
    if (threadIdx.x == 0) g_is64 = (red[0] == 0) ? 1 : 0;
}

__global__ void k_cvt(const void* __restrict__ ei) {
    int e = blockIdx.x * blockDim.x + threadIdx.x;
    if (e >= EE) return;
    if (g_is64) {
        const long long* p = (const long long*)ei;
        g_src[e] = (int)p[e];
        g_dst[e] = (int)p[EE + e];
    } else {
        const int* p = (const int*)ei;
        g_src[e] = p[e];
        g_dst[e] = p[EE + e];
    }
}

// ---------------- tiny edge-attr MLP (runs once, 1 block) --------------------
__global__ void k_ea(const float* __restrict__ nt, const float* __restrict__ et,
                     const float* __restrict__ mW1, const float* __restrict__ mb1,
                     const float* __restrict__ m_g, const float* __restrict__ m_b,
                     const float* __restrict__ m_m, const float* __restrict__ m_v,
                     const float* __restrict__ mW2, const float* __restrict__ mb2,
                     const float* __restrict__ qW,  const float* __restrict__ qb,
                     const float* __restrict__ kW,  const float* __restrict__ kb) {
    __shared__ float merged[2 * DD];
    __shared__ float h[DD];
    __shared__ float ea[DD];
    int t = threadIdx.x;  // 128 threads
    merged[t]      = nt[t];
    merged[t + DD] = et[t];
    __syncthreads();
    float s = mb1[t];
    for (int i = 0; i < 2 * DD; ++i) s = fmaf(merged[i], mW1[i * DD + t], s);
    float bn = (s - m_m[t]) * rsqrtf(m_v[t] + 1e-5f) * m_g[t] + m_b[t];
    h[t] = fmaxf(bn, 0.f);
    __syncthreads();
    float s2 = mb2[t];
    for (int i = 0; i < DD; ++i) s2 = fmaf(h[i], mW2[i * DD + t], s2);
    ea[t] = s2;
    __syncthreads();
    float sq = qb[t], sk = kb[t];
    for (int i = 0; i < DD; ++i) {
        sq = fmaf(ea[i], qW[i * DD + t], sq);
        sk = fmaf(ea[i], kW[i * DD + t], sk);
    }
    g_eaq[t] = sq;
    g_eak[t] = sk;
}

// ---------------- init softmax accumulators ----------------------------------
__global__ void k_init() {
    int i = blockIdx.x * blockDim.x + threadIdx.x;
    if (i < NN * HH) {
        g_smax[i] = (int)0x80000000;
        g_ssum[i] = 0.f;
    }
}

// ---------------- node projection GEMM: x @ {qW,kW,vW,resW} -------------------
// 128-row tile, 256 threads, 8x8 register block, strided (conflict-free) smem.
__global__ __launch_bounds__(256, 1)
void k_proj(const float* __restrict__ x,
            const float* __restrict__ qW, const float* __restrict__ kW,
            const float* __restrict__ vW, const float* __restrict__ resW,
            const float* __restrict__ vb) {
    extern __shared__ float sm[];
    float* As = sm;                 // [128][129] transposed: As[k*129+r] = x[r][k]
    float* Ws = sm + 128 * 129;     // [128][128]
    const int t  = threadIdx.x;
    const int ty = t >> 4, tx = t & 15;
    const int row0 = blockIdx.x * 128;

    for (int idx = t; idx < 128 * 128; idx += 256) {
        int r = idx >> 7, k = idx & 127;
        int gr = row0 + r;
        As[k * 129 + r] = (gr < NN) ? x[(size_t)gr * DD + k] : 0.f;
    }

    const float* Wg[4] = {qW, kW, vW, resW};
    float*       Og[4] = {g_Q, g_K, g_V, g_Z};

    for (int w = 0; w < 4; ++w) {
        __syncthreads();
        for (int idx = t * 4; idx < 128 * 128; idx += 1024)
            *(float4*)(Ws + idx) = *(const float4*)(Wg[w] + idx);
        __syncthreads();

        float acc[8][8];
        #pragma unroll
        for (int i = 0; i < 8; ++i)
            #pragma unroll
            for (int j = 0; j < 8; ++j) acc[i][j] = 0.f;

        #pragma unroll 4
        for (int k = 0; k < 128; ++k) {
            float a[8], b[8];
            #pragma unroll
            for (int i = 0; i < 8; ++i) a[i] = As[k * 129 + ty + 16 * i];
            #pragma unroll
            for (int j = 0; j < 8; ++j) b[j] = Ws[k * 128 + tx + 16 * j];
            #pragma unroll
            for (int i = 0; i < 8; ++i)
                #pragma unroll
                for (int j = 0; j < 8; ++j) acc[i][j] = fmaf(a[i], b[j], acc[i][j]);
        }

        float* O = Og[w];
        #pragma unroll
        for (int j = 0; j < 8; ++j) {
            int c = tx + 16 * j;
            float bv = (w == 2) ? vb[c] : 0.f;
            #pragma unroll
            for (int i = 0; i < 8; ++i) {
                int r = row0 + ty + 16 * i;
                if (r < NN) O[(size_t)r * DD + c] = acc[i][j] + bv;
            }
        }
    }
}

// ---------------- edge pass 1: scores + segment max (warp/edge) ---------------
__global__ void k_scores() {
    int gt = blockIdx.x * blockDim.x + threadIdx.x;
    int e = gt >> 5;
    int lane = gt & 31;
    if (e >= EE) return;
    int src = g_src[e];
    int dst = g_dst[e];

    float4 q4 = *(const float4*)(g_Q + (size_t)src * DD + lane * 4);
    float4 k4 = *(const float4*)(g_K + (size_t)dst * DD + lane * 4);
    float4 aq = *(const float4*)(g_eaq + lane * 4);
    float4 ak = *(const float4*)(g_eak + lane * 4);
    float p = (q4.x + aq.x) * (k4.x + ak.x)
            + (q4.y + aq.y) * (k4.y + ak.y)
            + (q4.z + aq.z) * (k4.z + ak.z)
            + (q4.w + aq.w) * (k4.w + ak.w);
    p += __shfl_xor_sync(0xffffffffu, p, 1);
    p += __shfl_xor_sync(0xffffffffu, p, 2);
    if ((lane & 3) == 0) {
        int h = lane >> 2;
        float s = p * 0.25f;   // 1/sqrt(DH=16)
        g_scores[(size_t)e * HH + h] = s;
        atomicMax(&g_smax[src * HH + h], f2o(s));
    }
}

// ---------------- edge pass 2: exp + segment sum ------------------------------
__global__ void k_exp() {
    int i = blockIdx.x * blockDim.x + threadIdx.x;
    if (i >= EE * HH) return;
    int e = i >> 3, h = i & 7;
    int src = g_src[e];
    float m = o2f(g_smax[src * HH + h]);
    float ex = expf(g_scores[i] - m);
    g_scores[i] = ex;
    atomicAdd(&g_ssum[src * HH + h], ex);
}

// ---------------- edge pass 3: weighted scatter-add (warp/edge) ---------------
__global__ void k_aggr() {
    int gt = blockIdx.x * blockDim.x + threadIdx.x;
    int e = gt >> 5;
    int lane = gt & 31;
    if (e >= EE) return;
    int src = g_src[e];
    int dst = g_dst[e];
    int h = lane >> 2;
    float alpha = g_scores[(size_t)e * HH + h] / g_ssum[src * HH + h];
    float4 v4 = *(const float4*)(g_V + (size_t)src * DD + lane * 4);
    float w0 = v4.x * alpha, w1 = v4.y * alpha, w2 = v4.z * alpha, w3 = v4.w * alpha;
    float* p = g_Z + (size_t)dst * DD + lane * 4;
    asm volatile("red.global.add.v4.f32 [%0], {%1, %2, %3, %4};"
                 :: "l"(p), "f"(w0), "f"(w1), "f"(w2), "f"(w3) : "memory");
}

// ---------------- fused output MLP: z@oW1 -> BN -> lrelu -> @oW2 --------------
__global__ __launch_bounds__(256, 1)
void k_out(const float* __restrict__ oW1, const float* __restrict__ ob1,
           const float* __restrict__ o_g, const float* __restrict__ o_b,
           const float* __restrict__ o_m, const float* __restrict__ o_v,
           const float* __restrict__ oW2, const float* __restrict__ ob2,
           float* __restrict__ out) {
    extern __shared__ float sm[];
    float* As = sm;                 // [128][129] transposed
    float* Ws = sm + 128 * 129;
    const int t  = threadIdx.x;
    const int ty = t >> 4, tx = t & 15;
    const int row0 = blockIdx.x * 128;

    for (int idx = t; idx < 128 * 128; idx += 256) {
        int r = idx >> 7, k = idx & 127;
        int gr = row0 + r;
        As[k * 129 + r] = (gr < NN) ? g_Z[(size_t)gr * DD + k] : 0.f;
    }
    for (int idx = t * 4; idx < 128 * 128; idx += 1024)
        *(float4*)(Ws + idx) = *(const float4*)(oW1 + idx);
    __syncthreads();

    float acc[8][8];
    #pragma unroll
    for (int i = 0; i < 8; ++i)
        #pragma unroll
        for (int j = 0; j < 8; ++j) acc[i][j] = 0.f;

    #pragma unroll 4
    for (int k = 0; k < 128; ++k) {
        float a[8], b[8];
        #pragma unroll
        for (int i = 0; i < 8; ++i) a[i] = As[k * 129 + ty + 16 * i];
        #pragma unroll
        for (int j = 0; j < 8; ++j) b[j] = Ws[k * 128 + tx + 16 * j];
        #pragma unroll
        for (int i = 0; i < 8; ++i)
            #pragma unroll
            for (int j = 0; j < 8; ++j) acc[i][j] = fmaf(a[i], b[j], acc[i][j]);
    }
    __syncthreads();   // all As reads done; safe to overwrite

    // BN + leaky ReLU, store transposed back into As for GEMM2
    #pragma unroll
    for (int j = 0; j < 8; ++j) {
        int c = tx + 16 * j;
        float sc = o_g[c] * rsqrtf(o_v[c] + 1e-5f);
        float sh = o_b[c] - o_m[c] * sc;
        float b1 = ob1[c];
        #pragma unroll
        for (int i = 0; i < 8; ++i) {
            float y = (acc[i][j] + b1) * sc + sh;
            y = (y > 0.f) ? y : 0.01f * y;
            As[c * 129 + ty + 16 * i] = y;
        }
    }
    for (int idx = t * 4; idx < 128 * 128; idx += 1024)
        *(float4*)(Ws + idx) = *(const float4*)(oW2 + idx);
    __syncthreads();

    #pragma unroll
    for (int i = 0; i < 8; ++i)
        #pragma unroll
        for (int j = 0; j < 8; ++j) acc[i][j] = 0.f;

    #pragma unroll 4
    for (int k = 0; k < 128; ++k) {
        float a[8], b[8];
        #pragma unroll
        for (int i = 0; i < 8; ++i) a[i] = As[k * 129 + ty + 16 * i];
        #pragma unroll
        for (int j = 0; j < 8; ++j) b[j] = Ws[k * 128 + tx + 16 * j];
        #pragma unroll
        for (int i = 0; i < 8; ++i)
            #pragma unroll
            for (int j = 0; j < 8; ++j) acc[i][j] = fmaf(a[i], b[j], acc[i][j]);
    }

    #pragma unroll
    for (int j = 0; j < 8; ++j) {
        int c = tx + 16 * j;
        float b2 = ob2[c];
        #pragma unroll
        for (int i = 0; i < 8; ++i) {
            int r = row0 + ty + 16 * i;
            if (r < NN) out[(size_t)r * DD + c] = acc[i][j] + b2;
        }
    }
}

// ---------------- launch ------------------------------------------------------
extern "C" void kernel_launch(void* const* d_in, const int* in_sizes, int n_in,
                              void* d_out, int out_size) {
    const float* x    = (const float*)d_in[0];
    const void*  ei   = d_in[1];
    const float* nt   = (const float*)d_in[2];
    const float* et   = (const float*)d_in[3];
    const float* mW1  = (const float*)d_in[4];
    const float* mb1  = (const float*)d_in[5];
    const float* m_g  = (const float*)d_in[6];
    const float* m_b  = (const float*)d_in[7];
    const float* m_m  = (const float*)d_in[8];
    const float* m_v  = (const float*)d_in[9];
    const float* mW2  = (const float*)d_in[10];
    const float* mb2  = (const float*)d_in[11];
    const float* resW = (const float*)d_in[12];
    const float* qW   = (const float*)d_in[13];
    const float* qb   = (const float*)d_in[14];
    const float* kW   = (const float*)d_in[15];
    const float* kb   = (const float*)d_in[16];
    const float* vW   = (const float*)d_in[17];
    const float* vb   = (const float*)d_in[18];
    const float* oW1  = (const float*)d_in[19];
    const float* ob1  = (const float*)d_in[20];
    const float* o_g  = (const float*)d_in[21];
    const float* o_b  = (const float*)d_in[22];
    const float* o_m  = (const float*)d_in[23];
    const float* o_v  = (const float*)d_in[24];
    const float* oW2  = (const float*)d_in[25];
    const float* ob2  = (const float*)d_in[26];
    float* out = (float*)d_out;

    const int SMEM = (128 * 129 + 128 * 128) * (int)sizeof(float);
    cudaFuncSetAttribute(k_proj, cudaFuncAttributeMaxDynamicSharedMemorySize, SMEM);
    cudaFuncSetAttribute(k_out,  cudaFuncAttributeMaxDynamicSharedMemorySize, SMEM);

    k_detect<<<1, 256>>>((const int*)ei);
    k_cvt<<<(EE + 255) / 256, 256>>>(ei);
    k_ea<<<1, 128>>>(nt, et, mW1, mb1, m_g, m_b, m_m, m_v, mW2, mb2, qW, qb, kW, kb);
    k_init<<<(NN * HH + 255) / 256, 256>>>();
    k_proj<<<(NN + 127) / 128, 256, SMEM>>>(x, qW, kW, vW, resW, vb);
    k_scores<<<(EE * 32 + 255) / 256, 256>>>();
    k_exp<<<(EE * HH + 255) / 256, 256>>>();
    k_aggr<<<(EE * 32 + 255) / 256, 256>>>();
    k_out<<<(NN + 127) / 128, 256, SMEM>>>(oW1, ob1, o_g, o_b, o_m, o_v, oW2, ob2, out);
}

// round 3
// speedup vs baseline: 1.6548x; 1.6548x over previous
#include <cuda_runtime.h>
#include <math.h>

#define NN 100000
#define DD 128
#define EE 600000
#define HH 8

#define PADA 132   // A/As row pitch (floats): frag bank = g*4+tg -> conflict-free
#define PADW 136   // W row pitch (floats):    frag bank = tg*8+g -> conflict-free

// ---------------- scratch (device globals; no allocation allowed) -------------
__device__ __align__(16) float g_Q[NN * DD];
__device__ __align__(16) float g_K[NN * DD];
__device__ __align__(16) float g_V[NN * DD];
__device__ __align__(16) float g_Z[NN * DD];   // residual, atomics add aggr
__device__ __align__(16) float g_scores[EE * HH];
__device__ int   g_smax[NN * HH];
__device__ float g_ssum[NN * HH];
__device__ __align__(16) float g_eaq[DD];
__device__ __align__(16) float g_eak[DD];
__device__ int g_src[EE];
__device__ int g_dst[EE];
__device__ int g_is64;

// ---------------- helpers ----------------------------------------------------
__device__ __forceinline__ int f2o(float f) {
    int i = __float_as_int(f);
    return (i >= 0) ? i : (i ^ 0x7fffffff);
}
__device__ __forceinline__ float o2f(int i) {
    return (i >= 0) ? __int_as_float(i) : __int_as_float(i ^ 0x7fffffff);
}
__device__ __forceinline__ unsigned f2tf(float f) {
    unsigned u;
    asm("cvt.rna.tf32.f32 %0, %1;" : "=r"(u) : "f"(f));
    return u;
}
__device__ __forceinline__ void mma_tf32(float* c, const unsigned* a, const unsigned* b) {
    asm volatile(
        "mma.sync.aligned.m16n8k8.row.col.f32.tf32.tf32.f32 "
        "{%0,%1,%2,%3}, {%4,%5,%6,%7}, {%8,%9}, {%0,%1,%2,%3};"
        : "+f"(c[0]), "+f"(c[1]), "+f"(c[2]), "+f"(c[3])
        : "r"(a[0]), "r"(a[1]), "r"(a[2]), "r"(a[3]), "r"(b[0]), "r"(b[1]));
}

// ---------------- dtype detect + index conversion -----------------------------
__global__ void k_detect(const int* __restrict__ w) {
    __shared__ int red[256];
    int acc = 0;
    for (int i = threadIdx.x; i < 4096; i += 256) acc |= w[2 * i + 1];
    red[threadIdx.x] = acc;
    __syncthreads();
    for (int s = 128; s > 0; s >>= 1) {
        if (threadIdx.x < s) red[threadIdx.x] |= red[threadIdx.x + s];
        __syncthreads();
    }
    if (threadIdx.x == 0) g_is64 = (red[0] == 0) ? 1 : 0;
}

__global__ void k_cvt(const void* __restrict__ ei) {
    int e = blockIdx.x * blockDim.x + threadIdx.x;
    if (e >= EE) return;
    if (g_is64) {
        const long long* p = (const long long*)ei;
        g_src[e] = (int)p[e];
        g_dst[e] = (int)p[EE + e];
    } else {
        const int* p = (const int*)ei;
        g_src[e] = p[e];
        g_dst[e] = p[EE + e];
    }
}

// ---------------- tiny edge-attr MLP (runs once, 1 block) --------------------
__global__ void k_ea(const float* __restrict__ nt, const float* __restrict__ et,
                     const float* __restrict__ mW1, const float* __restrict__ mb1,
                     const float* __restrict__ m_g, const float* __restrict__ m_b,
                     const float* __restrict__ m_m, const float* __restrict__ m_v,
                     const float* __restrict__ mW2, const float* __restrict__ mb2,
                     const float* __restrict__ qW,  const float* __restrict__ qb,
                     const float* __restrict__ kW,  const float* __restrict__ kb) {
    __shared__ float merged[2 * DD];
    __shared__ float h[DD];
    __shared__ float ea[DD];
    int t = threadIdx.x;  // 128 threads
    merged[t]      = nt[t];
    merged[t + DD] = et[t];
    __syncthreads();
    float s = mb1[t];
    for (int i = 0; i < 2 * DD; ++i) s = fmaf(merged[i], mW1[i * DD + t], s);
    float bn = (s - m_m[t]) * rsqrtf(m_v[t] + 1e-5f) * m_g[t] + m_b[t];
    h[t] = fmaxf(bn, 0.f);
    __syncthreads();
    float s2 = mb2[t];
    for (int i = 0; i < DD; ++i) s2 = fmaf(h[i], mW2[i * DD + t], s2);
    ea[t] = s2;
    __syncthreads();
    float sq = qb[t], sk = kb[t];
    for (int i = 0; i < DD; ++i) {
        sq = fmaf(ea[i], qW[i * DD + t], sq);
        sk = fmaf(ea[i], kW[i * DD + t], sk);
    }
    g_eaq[t] = sq;
    g_eak[t] = sk;
}

// ---------------- init softmax accumulators ----------------------------------
__global__ void k_init() {
    int i = blockIdx.x * blockDim.x + threadIdx.x;
    if (i < NN * HH) {
        g_smax[i] = (int)0x80000000;
        g_ssum[i] = 0.f;
    }
}

// ---------------- node projection GEMM (tf32 tensor cores) --------------------
// 128-row tile, 256 threads = 8 warps as 4M x 2N; warp tile 32x64.
__global__ __launch_bounds__(256, 1)
void k_proj(const float* __restrict__ x,
            const float* __restrict__ qW, const float* __restrict__ kW,
            const float* __restrict__ vW, const float* __restrict__ resW,
            const float* __restrict__ vb) {
    extern __shared__ float sm[];
    float* As = sm;                  // [128][PADA]
    float* Ws = sm + 128 * PADA;     // [128][PADW]
    const int t = threadIdx.x;
    const int warp = t >> 5, lane = t & 31;
    const int g = lane >> 2, tg = lane & 3;
    const int wm = warp >> 1, wn = warp & 1;
    const int row0 = blockIdx.x * 128;

    // stage x tile (tf32-rounded)
    for (int idx = t * 4; idx < 128 * 128; idx += 1024) {
        int r = idx >> 7, c = idx & 127;
        int gr = row0 + r;
        float4 v = (gr < NN) ? *(const float4*)(x + (size_t)gr * DD + c)
                             : make_float4(0.f, 0.f, 0.f, 0.f);
        uint4 u = make_uint4(f2tf(v.x), f2tf(v.y), f2tf(v.z), f2tf(v.w));
        *(uint4*)(As + r * PADA + c) = u;
    }

    const float* Wg[4] = {qW, kW, vW, resW};
    float*       Og[4] = {g_Q, g_K, g_V, g_Z};

    for (int w = 0; w < 4; ++w) {
        __syncthreads();
        for (int idx = t * 4; idx < 128 * 128; idx += 1024) {
            int r = idx >> 7, c = idx & 127;
            float4 v = *(const float4*)(Wg[w] + idx);
            uint4 u = make_uint4(f2tf(v.x), f2tf(v.y), f2tf(v.z), f2tf(v.w));
            *(uint4*)(Ws + r * PADW + c) = u;
        }
        __syncthreads();

        float acc[2][8][4];
        #pragma unroll
        for (int mt = 0; mt < 2; ++mt)
            #pragma unroll
            for (int nt = 0; nt < 8; ++nt)
                #pragma unroll
                for (int j = 0; j < 4; ++j) acc[mt][nt][j] = 0.f;

        const float* Abase = As + (wm * 32 + g) * PADA + tg;
        const float* Bbase = Ws + tg * PADW + wn * 64 + g;

        #pragma unroll 4
        for (int kk = 0; kk < 16; ++kk) {
            unsigned a[2][4], b[8][2];
            #pragma unroll
            for (int mt = 0; mt < 2; ++mt) {
                const float* p = Abase + mt * 16 * PADA + kk * 8;
                a[mt][0] = __float_as_uint(p[0]);
                a[mt][1] = __float_as_uint(p[8 * PADA]);
                a[mt][2] = __float_as_uint(p[4]);
                a[mt][3] = __float_as_uint(p[8 * PADA + 4]);
            }
            #pragma unroll
            for (int nt = 0; nt < 8; ++nt) {
                const float* p = Bbase + kk * 8 * PADW + nt * 8;
                b[nt][0] = __float_as_uint(p[0]);
                b[nt][1] = __float_as_uint(p[4 * PADW]);
            }
            #pragma unroll
            for (int mt = 0; mt < 2; ++mt)
                #pragma unroll
                for (int nt = 0; nt < 8; ++nt)
                    mma_tf32(acc[mt][nt], a[mt], b[nt]);
        }

        float* O = Og[w];
        #pragma unroll
        for (int mt = 0; mt < 2; ++mt) {
            int r = row0 + wm * 32 + mt * 16 + g;
            #pragma unroll
            for (int nt = 0; nt < 8; ++nt) {
                int c = wn * 64 + nt * 8 + tg * 2;
                float bv0 = 0.f, bv1 = 0.f;
                if (w == 2) { bv0 = vb[c]; bv1 = vb[c + 1]; }
                if (r < NN)
                    *(float2*)(O + (size_t)r * DD + c) =
                        make_float2(acc[mt][nt][0] + bv0, acc[mt][nt][1] + bv1);
                if (r + 8 < NN)
                    *(float2*)(O + (size_t)(r + 8) * DD + c) =
                        make_float2(acc[mt][nt][2] + bv0, acc[mt][nt][3] + bv1);
            }
        }
    }
}

// ---------------- edge pass 1: scores + segment max (warp/edge) ---------------
__global__ void k_scores() {
    int gt = blockIdx.x * blockDim.x + threadIdx.x;
    int e = gt >> 5;
    int lane = gt & 31;
    if (e >= EE) return;
    int src = g_src[e];
    int dst = g_dst[e];

    float4 q4 = *(const float4*)(g_Q + (size_t)src * DD + lane * 4);
    float4 k4 = *(const float4*)(g_K + (size_t)dst * DD + lane * 4);
    float4 aq = *(const float4*)(g_eaq + lane * 4);
    float4 ak = *(const float4*)(g_eak + lane * 4);
    float p = (q4.x + aq.x) * (k4.x + ak.x)
            + (q4.y + aq.y) * (k4.y + ak.y)
            + (q4.z + aq.z) * (k4.z + ak.z)
            + (q4.w + aq.w) * (k4.w + ak.w);
    p += __shfl_xor_sync(0xffffffffu, p, 1);
    p += __shfl_xor_sync(0xffffffffu, p, 2);
    if ((lane & 3) == 0) {
        int h = lane >> 2;
        float s = p * 0.25f;   // 1/sqrt(DH=16)
        g_scores[(size_t)e * HH + h] = s;
        atomicMax(&g_smax[src * HH + h], f2o(s));
    }
}

// ---------------- edge pass 2: exp + segment sum ------------------------------
__global__ void k_exp() {
    int i = blockIdx.x * blockDim.x + threadIdx.x;
    if (i >= EE * HH) return;
    int e = i >> 3, h = i & 7;
    int src = g_src[e];
    float m = o2f(g_smax[src * HH + h]);
    float ex = expf(g_scores[i] - m);
    g_scores[i] = ex;
    atomicAdd(&g_ssum[src * HH + h], ex);
}

// ---------------- edge pass 3: weighted scatter-add (warp/edge) ---------------
__global__ void k_aggr() {
    int gt = blockIdx.x * blockDim.x + threadIdx.x;
    int e = gt >> 5;
    int lane = gt & 31;
    if (e >= EE) return;
    int src = g_src[e];
    int dst = g_dst[e];
    int h = lane >> 2;
    float alpha = g_scores[(size_t)e * HH + h] / g_ssum[src * HH + h];
    float4 v4 = *(const float4*)(g_V + (size_t)src * DD + lane * 4);
    float w0 = v4.x * alpha, w1 = v4.y * alpha, w2 = v4.z * alpha, w3 = v4.w * alpha;
    float* p = g_Z + (size_t)dst * DD + lane * 4;
    asm volatile("red.global.add.v4.f32 [%0], {%1, %2, %3, %4};"
                 :: "l"(p), "f"(w0), "f"(w1), "f"(w2), "f"(w3) : "memory");
}

// ---------------- fused output MLP (tf32 tensor cores) ------------------------
__global__ __launch_bounds__(256, 1)
void k_out(const float* __restrict__ oW1, const float* __restrict__ ob1,
           const float* __restrict__ o_g, const float* __restrict__ o_b,
           const float* __restrict__ o_m, const float* __restrict__ o_v,
           const float* __restrict__ oW2, const float* __restrict__ ob2,
           float* __restrict__ out) {
    extern __shared__ float sm[];
    float* As  = sm;                        // [128][PADA]
    float* Ws  = sm + 128 * PADA;           // [128][PADW]
    float* bnS = Ws + 128 * PADW;           // sc[128], sh[128], b1[128]
    const int t = threadIdx.x;
    const int warp = t >> 5, lane = t & 31;
    const int g = lane >> 2, tg = lane & 3;
    const int wm = warp >> 1, wn = warp & 1;
    const int row0 = blockIdx.x * 128;

    // stage Z tile (tf32), oW1, and BN constants
    for (int idx = t * 4; idx < 128 * 128; idx += 1024) {
        int r = idx >> 7, c = idx & 127;
        int gr = row0 + r;
        float4 v = (gr < NN) ? *(const float4*)(g_Z + (size_t)gr * DD + c)
                             : make_float4(0.f, 0.f, 0.f, 0.f);
        uint4 u = make_uint4(f2tf(v.x), f2tf(v.y), f2tf(v.z), f2tf(v.w));
        *(uint4*)(As + r * PADA + c) = u;
        float4 wv = *(const float4*)(oW1 + idx);
        uint4 wu = make_uint4(f2tf(wv.x), f2tf(wv.y), f2tf(wv.z), f2tf(wv.w));
        *(uint4*)(Ws + r * PADW + c) = wu;
    }
    if (t < 128) {
        float sc = o_g[t] * rsqrtf(o_v[t] + 1e-5f);
        bnS[t]       = sc;
        bnS[128 + t] = o_b[t] - o_m[t] * sc;
        bnS[256 + t] = ob1[t];
    }
    __syncthreads();

    float acc[2][8][4];
    #pragma unroll
    for (int mt = 0; mt < 2; ++mt)
        #pragma unroll
        for (int nt = 0; nt < 8; ++nt)
            #pragma unroll
            for (int j = 0; j < 4; ++j) acc[mt][nt][j] = 0.f;

    const float* Abase = As + (wm * 32 + g) * PADA + tg;
    const float* Bbase = Ws + tg * PADW + wn * 64 + g;

    #pragma unroll 4
    for (int kk = 0; kk < 16; ++kk) {
        unsigned a[2][4], b[8][2];
        #pragma unroll
        for (int mt = 0; mt < 2; ++mt) {
            const float* p = Abase + mt * 16 * PADA + kk * 8;
            a[mt][0] = __float_as_uint(p[0]);
            a[mt][1] = __float_as_uint(p[8 * PADA]);
            a[mt][2] = __float_as_uint(p[4]);
            a[mt][3] = __float_as_uint(p[8 * PADA + 4]);
        }
        #pragma unroll
        for (int nt = 0; nt < 8; ++nt) {
            const float* p = Bbase + kk * 8 * PADW + nt * 8;
            b[nt][0] = __float_as_uint(p[0]);
            b[nt][1] = __float_as_uint(p[4 * PADW]);
        }
        #pragma unroll
        for (int mt = 0; mt < 2; ++mt)
            #pragma unroll
            for (int nt = 0; nt < 8; ++nt)
                mma_tf32(acc[mt][nt], a[mt], b[nt]);
    }
    __syncthreads();   // all As(Z) reads done

    // BN + leakyReLU on fragments, re-stage Y (tf32) into As
    #pragma unroll
    for (int mt = 0; mt < 2; ++mt) {
        int rl = wm * 32 + mt * 16 + g;
        #pragma unroll
        for (int nt = 0; nt < 8; ++nt) {
            int c = wn * 64 + nt * 8 + tg * 2;
            float sc0 = bnS[c],       sc1 = bnS[c + 1];
            float sh0 = bnS[128 + c], sh1 = bnS[129 + c];
            float b10 = bnS[256 + c], b11 = bnS[257 + c];
            float y0 = (acc[mt][nt][0] + b10) * sc0 + sh0;
            float y1 = (acc[mt][nt][1] + b11) * sc1 + sh1;
            float y2 = (acc[mt][nt][2] + b10) * sc0 + sh0;
            float y3 = (acc[mt][nt][3] + b11) * sc1 + sh1;
            y0 = (y0 > 0.f) ? y0 : 0.01f * y0;
            y1 = (y1 > 0.f) ? y1 : 0.01f * y1;
            y2 = (y2 > 0.f) ? y2 : 0.01f * y2;
            y3 = (y3 > 0.f) ? y3 : 0.01f * y3;
            *(uint2*)(As + rl * PADA + c)       = make_uint2(f2tf(y0), f2tf(y1));
            *(uint2*)(As + (rl + 8) * PADA + c) = make_uint2(f2tf(y2), f2tf(y3));
        }
    }
    // stage oW2
    for (int idx = t * 4; idx < 128 * 128; idx += 1024) {
        int r = idx >> 7, c = idx & 127;
        float4 wv = *(const float4*)(oW2 + idx);
        uint4 wu = make_uint4(f2tf(wv.x), f2tf(wv.y), f2tf(wv.z), f2tf(wv.w));
        *(uint4*)(Ws + r * PADW + c) = wu;
    }
    __syncthreads();

    #pragma unroll
    for (int mt = 0; mt < 2; ++mt)
        #pragma unroll
        for (int nt = 0; nt < 8; ++nt)
            #pragma unroll
            for (int j = 0; j < 4; ++j) acc[mt][nt][j] = 0.f;

    #pragma unroll 4
    for (int kk = 0; kk < 16; ++kk) {
        unsigned a[2][4], b[8][2];
        #pragma unroll
        for (int mt = 0; mt < 2; ++mt) {
            const float* p = Abase + mt * 16 * PADA + kk * 8;
            a[mt][0] = __float_as_uint(p[0]);
            a[mt][1] = __float_as_uint(p[8 * PADA]);
            a[mt][2] = __float_as_uint(p[4]);
            a[mt][3] = __float_as_uint(p[8 * PADA + 4]);
        }
        #pragma unroll
        for (int nt = 0; nt < 8; ++nt) {
            const float* p = Bbase + kk * 8 * PADW + nt * 8;
            b[nt][0] = __float_as_uint(p[0]);
            b[nt][1] = __float_as_uint(p[4 * PADW]);
        }
        #pragma unroll
        for (int mt = 0; mt < 2; ++mt)
            #pragma unroll
            for (int nt = 0; nt < 8; ++nt)
                mma_tf32(acc[mt][nt], a[mt], b[nt]);
    }

    #pragma unroll
    for (int mt = 0; mt < 2; ++mt) {
        int r = row0 + wm * 32 + mt * 16 + g;
        #pragma unroll
        for (int nt = 0; nt < 8; ++nt) {
            int c = wn * 64 + nt * 8 + tg * 2;
            float b20 = ob2[c], b21 = ob2[c + 1];
            if (r < NN)
                *(float2*)(out + (size_t)r * DD + c) =
                    make_float2(acc[mt][nt][0] + b20, acc[mt][nt][1] + b21);
            if (r + 8 < NN)
                *(float2*)(out + (size_t)(r + 8) * DD + c) =
                    make_float2(acc[mt][nt][2] + b20, acc[mt][nt][3] + b21);
        }
    }
}

// ---------------- launch ------------------------------------------------------
extern "C" void kernel_launch(void* const* d_in, const int* in_sizes, int n_in,
                              void* d_out, int out_size) {
    const float* x    = (const float*)d_in[0];
    const void*  ei   = d_in[1];
    const float* nt   = (const float*)d_in[2];
    const float* et   = (const float*)d_in[3];
    const float* mW1  = (const float*)d_in[4];
    const float* mb1  = (const float*)d_in[5];
    const float* m_g  = (const float*)d_in[6];
    const float* m_b  = (const float*)d_in[7];
    const float* m_m  = (const float*)d_in[8];
    const float* m_v  = (const float*)d_in[9];
    const float* mW2  = (const float*)d_in[10];
    const float* mb2  = (const float*)d_in[11];
    const float* resW = (const float*)d_in[12];
    const float* qW   = (const float*)d_in[13];
    const float* qb   = (const float*)d_in[14];
    const float* kW   = (const float*)d_in[15];
    const float* kb   = (const float*)d_in[16];
    const float* vW   = (const float*)d_in[17];
    const float* vb   = (const float*)d_in[18];
    const float* oW1  = (const float*)d_in[19];
    const float* ob1  = (const float*)d_in[20];
    const float* o_g  = (const float*)d_in[21];
    const float* o_b  = (const float*)d_in[22];
    const float* o_m  = (const float*)d_in[23];
    const float* o_v  = (const float*)d_in[24];
    const float* oW2  = (const float*)d_in[25];
    const float* ob2  = (const float*)d_in[26];
    float* out = (float*)d_out;

    const int SMEM_P = (128 * PADA + 128 * PADW) * (int)sizeof(float);
    const int SMEM_O = (128 * PADA + 128 * PADW + 3 * 128) * (int)sizeof(float);
    cudaFuncSetAttribute(k_proj, cudaFuncAttributeMaxDynamicSharedMemorySize, SMEM_P);
    cudaFuncSetAttribute(k_out,  cudaFuncAttributeMaxDynamicSharedMemorySize, SMEM_O);

    k_detect<<<1, 256>>>((const int*)ei);
    k_cvt<<<(EE + 255) / 256, 256>>>(ei);
    k_ea<<<1, 128>>>(nt, et, mW1, mb1, m_g, m_b, m_m, m_v, mW2, mb2, qW, qb, kW, kb);
    k_init<<<(NN * HH + 255) / 256, 256>>>();
    k_proj<<<(NN + 127) / 128, 256, SMEM_P>>>(x, qW, kW, vW, resW, vb);
    k_scores<<<(EE * 32 + 255) / 256, 256>>>();
    k_exp<<<(EE * HH + 255) / 256, 256>>>();
    k_aggr<<<(EE * 32 + 255) / 256, 256>>>();
    k_out<<<(NN + 127) / 128, 256, SMEM_O>>>(oW1, ob1, o_g, o_b, o_m, o_v, oW2, ob2, out);
}